// round 15
// baseline (speedup 1.0000x reference)
#include <cuda_runtime.h>
#include <cuda_fp16.h>
#include <math.h>
#include <stdint.h>

#define Bc  2
#define Sc  2048
#define Dc  1024
#define Hc  16
#define HDc 64

// Scratch (allocation-free).
__device__ __align__(16) __half g_xh[Bc*Sc*Dc];     // x as fp16 [B*S][D]
__device__ __align__(16) __half g_wh[4*Dc*Dc];      // Wq,Wk,Wv,Wg fp16 [n][k]
__device__ float               g_gf[Bc*Sc*Dc];      // g proj fp32, head-major
__device__ __align__(16) __half g_qh[Bc*Sc*Dc];     // gelu(q*g) fp16, head-major
__device__ __align__(16) __half g_kh[Bc*Sc*Dc];     // k fp16, head-major
__device__ __align__(16) __half g_vh[Bc*Sc*Dc];     // v fp16, head-major

// ---------------------------------------------------------------------------
// PTX helpers (all sm_80-era, legal in compute_103 PTX)
// ---------------------------------------------------------------------------
__device__ __forceinline__ uint32_t smem_u32(const void* p) {
    uint32_t a;
    asm("{ .reg .u64 t; cvta.to.shared.u64 t, %1; cvt.u32.u64 %0, t; }"
        : "=r"(a) : "l"(p));
    return a;
}

__device__ __forceinline__ void ldsm4(uint32_t r[4], uint32_t addr) {
    asm volatile("ldmatrix.sync.aligned.m8n8.x4.shared.b16 {%0,%1,%2,%3}, [%4];"
                 : "=r"(r[0]), "=r"(r[1]), "=r"(r[2]), "=r"(r[3]) : "r"(addr));
}

__device__ __forceinline__ void ldsm4t(uint32_t r[4], uint32_t addr) {
    asm volatile("ldmatrix.sync.aligned.m8n8.x4.trans.shared.b16 {%0,%1,%2,%3}, [%4];"
                 : "=r"(r[0]), "=r"(r[1]), "=r"(r[2]), "=r"(r[3]) : "r"(addr));
}

// D += A(16x16) * B(16x8); fp16 inputs, fp32 accumulate.
__device__ __forceinline__ void mma16(float c[4], const uint32_t a[4],
                                      uint32_t b0, uint32_t b1) {
    asm volatile(
        "mma.sync.aligned.m16n8k16.row.col.f32.f16.f16.f32 "
        "{%0,%1,%2,%3}, {%4,%5,%6,%7}, {%8,%9}, {%0,%1,%2,%3};"
        : "+f"(c[0]), "+f"(c[1]), "+f"(c[2]), "+f"(c[3])
        : "r"(a[0]), "r"(a[1]), "r"(a[2]), "r"(a[3]), "r"(b0), "r"(b1));
}

__device__ __forceinline__ void cp16(uint32_t dst, const void* src) {
    asm volatile("cp.async.cg.shared.global [%0], [%1], 16;"
                 :: "r"(dst), "l"(src) : "memory");
}
#define CP_COMMIT() asm volatile("cp.async.commit_group;" ::: "memory")
#define CP_WAIT1()  asm volatile("cp.async.wait_group 1;" ::: "memory")
#define CP_WAIT0()  asm volatile("cp.async.wait_group 0;" ::: "memory")

__device__ __forceinline__ uint32_t packh2(float a, float b) {
    __half2 h = __floats2half2_rn(a, b);
    return *reinterpret_cast<uint32_t*>(&h);
}

// pack (lo,hi) floats -> f16x2, lo in bits[0:15]
__device__ __forceinline__ uint32_t cvt_f16x2(float lo, float hi) {
    uint32_t r;
    asm("cvt.rn.f16x2.f32 %0, %1, %2;" : "=r"(r) : "f"(hi), "f"(lo));
    return r;
}

// elementwise 2^x on f16x2 (MUFU, one op per pair)
__device__ __forceinline__ uint32_t ex2h2(uint32_t t) {
    uint32_t r;
    asm("ex2.approx.f16x2 %0, %1;" : "=r"(r) : "r"(t));
    return r;
}

#define ONES_H2 0x3C003C00u   // half2(1.0, 1.0)
#define L2E     1.4426950408889634f

__device__ __forceinline__ float gelu_exact(float x) {
    return 0.5f * x * (1.0f + erff(x * 0.7071067811865476f));
}

// ---------------------------------------------------------------------------
// Pre-convert x and W to fp16. grid (1024, 5); 16B packed stores.
// ---------------------------------------------------------------------------
__global__ __launch_bounds__(256)
void cvt_kernel(const float* __restrict__ x,
                const float* __restrict__ Wq, const float* __restrict__ Wk,
                const float* __restrict__ Wv, const float* __restrict__ Wg)
{
    int z = blockIdx.y;
    const float* src; __half* dst; int n8;
    if (z == 0)      { src = x;  dst = g_xh;               n8 = Bc*Sc*Dc/8; }
    else if (z == 1) { src = Wq; dst = g_wh + 0*Dc*Dc;     n8 = Dc*Dc/8; }
    else if (z == 2) { src = Wk; dst = g_wh + 1*Dc*Dc;     n8 = Dc*Dc/8; }
    else if (z == 3) { src = Wv; dst = g_wh + 2*Dc*Dc;     n8 = Dc*Dc/8; }
    else             { src = Wg; dst = g_wh + 3*Dc*Dc;     n8 = Dc*Dc/8; }
    #pragma unroll
    for (int r = 0; r < 2; r++) {
        int i = blockIdx.x * 512 + r * 256 + threadIdx.x;
        if (i < n8) {
            float4 v0 = ((const float4*)src)[2*i];
            float4 v1 = ((const float4*)src)[2*i + 1];
            uint4 pk;
            pk.x = packh2(v0.x, v0.y);
            pk.y = packh2(v0.z, v0.w);
            pk.z = packh2(v1.x, v1.y);
            pk.w = packh2(v1.z, v1.w);
            ((uint4*)dst)[i] = pk;
        }
    }
}

// ===========================================================================
// Shared GEMM mainloop (R12's proven 3-stage cp.async ring, 1 sync/iter).
// Computes acc[2][8][4] = X[m0:m0+128] @ W[n0:n0+128]^T for one weight matrix.
// ===========================================================================
#define PR_STRIDE 40
#define PR_BUF_H  (128 * PR_STRIDE)
#define PR_SMEM_BYTES (6 * PR_BUF_H * 2)     // 61440

__device__ __forceinline__ void gemm_mainloop(
    const __half* Wg_, int m0, int n0, uint32_t xb, uint32_t wb,
    int tid, int lane, int wm, int wn, float acc[2][8][4])
{
    const int srow = tid >> 2;
    const int sc4  = tid & 3;

    #pragma unroll
    for (int p = 0; p < 2; p++) {
        const uint32_t boff = (uint32_t)(p * PR_BUF_H) * 2;
        #pragma unroll
        for (int r = 0; r < 2; r++) {
            int row = srow + r * 64;
            uint32_t d = boff + (uint32_t)(row * PR_STRIDE + sc4 * 8) * 2;
            cp16(xb + d, g_xh + (size_t)(m0 + row) * Dc + p * 32 + sc4 * 8);
            cp16(wb + d, Wg_ + (size_t)(n0 + row) * Dc + p * 32 + sc4 * 8);
        }
        CP_COMMIT();
    }

    int bi = 0, si = 2;
    for (int it = 0; it < 32; it++) {
        if (it < 31) { CP_WAIT1(); } else { CP_WAIT0(); }
        __syncthreads();

        if (it + 2 < 32) {
            const int k0 = (it + 2) * 32;
            const uint32_t xoff = xb + (uint32_t)(si * PR_BUF_H) * 2;
            const uint32_t woff = wb + (uint32_t)(si * PR_BUF_H) * 2;
            #pragma unroll
            for (int r = 0; r < 2; r++) {
                int row = srow + r * 64;
                uint32_t d = (uint32_t)(row * PR_STRIDE + sc4 * 8) * 2;
                cp16(xoff + d, g_xh + (size_t)(m0 + row) * Dc + k0 + sc4 * 8);
                cp16(woff + d, Wg_ + (size_t)(n0 + row) * Dc + k0 + sc4 * 8);
            }
            CP_COMMIT();
        }

        const uint32_t xab = xb + (uint32_t)(bi * PR_BUF_H) * 2;
        const uint32_t wab = wb + (uint32_t)(bi * PR_BUF_H) * 2;
        #pragma unroll
        for (int kk = 0; kk < 2; kk++) {
            uint32_t a[2][4];
            #pragma unroll
            for (int mi = 0; mi < 2; mi++) {
                int row = wm * 32 + mi * 16 + (lane & 15);
                ldsm4(a[mi], xab + (uint32_t)(row * PR_STRIDE + kk * 16 + (lane >> 4) * 8) * 2);
            }
            #pragma unroll
            for (int np = 0; np < 4; np++) {
                int g   = lane >> 3;
                int row = wn * 64 + np * 16 + (g >> 1) * 8 + (lane & 7);
                uint32_t bb[4];
                ldsm4(bb, wab + (uint32_t)(row * PR_STRIDE + kk * 16 + (g & 1) * 8) * 2);
                mma16(acc[0][2*np],   a[0], bb[0], bb[1]);
                mma16(acc[1][2*np],   a[1], bb[0], bb[1]);
                mma16(acc[0][2*np+1], a[0], bb[2], bb[3]);
                mma16(acc[1][2*np+1], a[1], bb[2], bb[3]);
            }
        }
        bi = (bi == 2) ? 0 : bi + 1;
        si = (si == 2) ? 0 : si + 1;
    }
}

// ===========================================================================
// Launch 1: K, V (fp16 out) and G (fp32 out). blockIdx.z: 0->K, 1->V, 2->G.
// ===========================================================================
__global__ __launch_bounds__(256, 2)
void proj_kvg(const float* __restrict__ bk, const float* __restrict__ bv,
              const float* __restrict__ bg)
{
    extern __shared__ __half psm[];

    const int z = blockIdx.z;
    const __half* Wg_ = g_wh + (size_t)(z + 1) * Dc * Dc;   // Wk, Wv, Wg
    const float* bias = (z == 0) ? bk : (z == 1) ? bv : bg;

    const int tid  = threadIdx.x;
    const int lane = tid & 31;
    const int wid  = tid >> 5;
    const int wm   = wid & 3;
    const int wn   = wid >> 2;
    const int m0   = blockIdx.y * 128;
    const int n0   = blockIdx.x * 128;
    const int lq   = lane >> 2;
    const int lr   = lane & 3;

    const uint32_t xb = smem_u32(psm);
    const uint32_t wb = xb + 3 * PR_BUF_H * 2;

    float acc[2][8][4] = {};
    gemm_mainloop(Wg_, m0, n0, xb, wb, tid, lane, wm, wn, acc);

    #pragma unroll
    for (int ni = 0; ni < 8; ni++) {
        int col = n0 + wn * 64 + ni * 8 + lr * 2;
        float bx = bias[col], by = bias[col + 1];
        int h  = col >> 6;
        int d0 = col & 63;
        #pragma unroll
        for (int mi = 0; mi < 2; mi++) {
            int mA = m0 + wm * 32 + mi * 16 + lq;
            int mB = mA + 8;
            size_t iA = ((size_t)((mA >> 11) * Hc + h) * Sc + (mA & 2047)) * HDc + d0;
            size_t iB = ((size_t)((mB >> 11) * Hc + h) * Sc + (mB & 2047)) * HDc + d0;
            float a0 = acc[mi][ni][0] + bx, a1 = acc[mi][ni][1] + by;
            float a2 = acc[mi][ni][2] + bx, a3 = acc[mi][ni][3] + by;
            if (z == 0) {
                *(__half2*)(g_kh + iA) = __floats2half2_rn(a0, a1);
                *(__half2*)(g_kh + iB) = __floats2half2_rn(a2, a3);
            } else if (z == 1) {
                *(__half2*)(g_vh + iA) = __floats2half2_rn(a0, a1);
                *(__half2*)(g_vh + iB) = __floats2half2_rn(a2, a3);
            } else {
                *(float2*)(g_gf + iA) = make_float2(a0, a1);
                *(float2*)(g_gf + iB) = make_float2(a2, a3);
            }
        }
    }
}

// ===========================================================================
// Launch 2: Q GEMM with FUSED GATE epilogue: qg = gelu(q * g) -> fp16 g_qh.
// Reads g (fp32) written by launch 1 at the same head-major indices.
// ===========================================================================
__global__ __launch_bounds__(256, 2)
void proj_q(const float* __restrict__ bq)
{
    extern __shared__ __half psm[];

    const __half* Wg_ = g_wh;                 // Wq at offset 0
    const int tid  = threadIdx.x;
    const int lane = tid & 31;
    const int wid  = tid >> 5;
    const int wm   = wid & 3;
    const int wn   = wid >> 2;
    const int m0   = blockIdx.y * 128;
    const int n0   = blockIdx.x * 128;
    const int lq   = lane >> 2;
    const int lr   = lane & 3;

    const uint32_t xb = smem_u32(psm);
    const uint32_t wb = xb + 3 * PR_BUF_H * 2;

    float acc[2][8][4] = {};
    gemm_mainloop(Wg_, m0, n0, xb, wb, tid, lane, wm, wn, acc);

    #pragma unroll
    for (int ni = 0; ni < 8; ni++) {
        int col = n0 + wn * 64 + ni * 8 + lr * 2;
        float bx = bq[col], by = bq[col + 1];
        int h  = col >> 6;
        int d0 = col & 63;
        #pragma unroll
        for (int mi = 0; mi < 2; mi++) {
            int mA = m0 + wm * 32 + mi * 16 + lq;
            int mB = mA + 8;
            size_t iA = ((size_t)((mA >> 11) * Hc + h) * Sc + (mA & 2047)) * HDc + d0;
            size_t iB = ((size_t)((mB >> 11) * Hc + h) * Sc + (mB & 2047)) * HDc + d0;
            float2 gA = *(const float2*)(g_gf + iA);
            float2 gB = *(const float2*)(g_gf + iB);
            float a0 = acc[mi][ni][0] + bx, a1 = acc[mi][ni][1] + by;
            float a2 = acc[mi][ni][2] + bx, a3 = acc[mi][ni][3] + by;
            *(__half2*)(g_qh + iA) =
                __floats2half2_rn(gelu_exact(a0 * gA.x), gelu_exact(a1 * gA.y));
            *(__half2*)(g_qh + iB) =
                __floats2half2_rn(gelu_exact(a2 * gB.x), gelu_exact(a3 * gB.y));
        }
    }
}

// ===========================================================================
// Flash attention — R12 compute verbatim; Q now staged by cp.async from g_qh
// (gate already applied in proj_q). 2-buffer KV, Q fragments hoisted,
// f16x2 exp, tensor-pipe row sums.
// ===========================================================================
#define AT_S   72
#define QS_H   0
#define KS_H   (128 * AT_S)                 // 9216
#define VS_H   (KS_H + 2 * 64 * AT_S)       // 18432
#define AT_SMEM_BYTES ((VS_H + 2 * 64 * AT_S) * 2)   // 55296

__global__ __launch_bounds__(128, 2)
void attn_h(float* __restrict__ out)
{
    extern __shared__ __half sh[];
    const uint32_t sb = smem_u32(sh);

    const int tid  = threadIdx.x;
    const int lane = tid & 31;
    const int wid  = tid >> 5;
    const int lq   = lane >> 2;
    const int lr   = lane & 3;
    const int qt   = blockIdx.x;      // 0..15
    const int bh   = blockIdx.y;      // 0..31

    const __half* Qg = g_qh + ((size_t)bh * Sc + (size_t)qt * 128) * HDc;
    const __half* Kg = g_kh + (size_t)bh * Sc * HDc;
    const __half* Vg = g_vh + (size_t)bh * Sc * HDc;

    // Stage Q (cp.async, 8 chunks/thread) + KV tile 0, single commit group.
    {
        const int qrow = tid >> 3;       // 0..15 base row (8 phases of 16)
        const int qc8  = tid & 7;
        #pragma unroll
        for (int r = 0; r < 8; r++) {
            int row = qrow + r * 16;
            cp16(sb + (uint32_t)(QS_H + row * AT_S + qc8 * 8) * 2,
                 Qg + (size_t)row * HDc + qc8 * 8);
        }
        #pragma unroll
        for (int r = 0; r < 4; r++) {
            int row = qrow + r * 16;
            uint32_t d = (uint32_t)(row * AT_S + qc8 * 8) * 2;
            cp16(sb + KS_H * 2 + d, Kg + (size_t)row * HDc + qc8 * 8);
            cp16(sb + VS_H * 2 + d, Vg + (size_t)row * HDc + qc8 * 8);
        }
    }
    CP_COMMIT();
    CP_WAIT0();
    __syncthreads();

    // Q fragments hoisted into registers (loaded ONCE, reused 32 iterations).
    uint32_t qfr[4][2][4];    // [kk][mi][reg]
    #pragma unroll
    for (int kk = 0; kk < 4; kk++) {
        #pragma unroll
        for (int mi = 0; mi < 2; mi++) {
            int row = wid * 32 + mi * 16 + (lane & 15);
            ldsm4(qfr[kk][mi],
                  sb + (uint32_t)(QS_H + row * AT_S + kk * 16 + (lane >> 4) * 8) * 2);
        }
    }

    float o[2][8][4] = {};
    float lacc[2][4] = {};                       // row sums via ones-mma
    float mrow[4] = {-1e30f, -1e30f, -1e30f, -1e30f};

    for (int kt = 0; kt < Sc / 64; kt++) {
        const int buf = kt & 1;
        if (kt + 1 < Sc / 64) {
            const int srow = tid >> 3;
            const int sc8  = tid & 7;
            const uint32_t boff = (uint32_t)((buf ^ 1) * 64 * AT_S) * 2;
            const __half* Kt = Kg + (size_t)(kt + 1) * 64 * HDc;
            const __half* Vt = Vg + (size_t)(kt + 1) * 64 * HDc;
            #pragma unroll
            for (int r = 0; r < 4; r++) {
                int row = srow + r * 16;
                uint32_t d = (uint32_t)(row * AT_S + sc8 * 8) * 2;
                cp16(sb + KS_H * 2 + boff + d, Kt + (size_t)row * HDc + sc8 * 8);
                cp16(sb + VS_H * 2 + boff + d, Vt + (size_t)row * HDc + sc8 * 8);
            }
            CP_COMMIT();
            CP_WAIT1();
        } else {
            CP_WAIT0();
        }
        __syncthreads();

        const uint32_t kab = sb + (uint32_t)(KS_H + buf * 64 * AT_S) * 2;
        const uint32_t vab = sb + (uint32_t)(VS_H + buf * 64 * AT_S) * 2;

        // S = Q @ K^T : 32q x 64t, k = d = 64 (4 k16 steps), Q from registers.
        float scf[2][8][4] = {};
        #pragma unroll
        for (int kk = 0; kk < 4; kk++) {
            #pragma unroll
            for (int np = 0; np < 4; np++) {
                int g   = lane >> 3;
                int row = np * 16 + (g >> 1) * 8 + (lane & 7);
                uint32_t bb[4];
                ldsm4(bb, kab + (uint32_t)(row * AT_S + kk * 16 + (g & 1) * 8) * 2);
                mma16(scf[0][2*np],   qfr[kk][0], bb[0], bb[1]);
                mma16(scf[1][2*np],   qfr[kk][1], bb[0], bb[1]);
                mma16(scf[0][2*np+1], qfr[kk][0], bb[2], bb[3]);
                mma16(scf[1][2*np+1], qfr[kk][1], bb[2], bb[3]);
            }
        }

        // Online softmax: p = exp2((s - m)*log2e) in f16x2 (one MUFU per pair),
        // packed into PV A-fragments. Row sums via ones-mma (below).
        uint32_t pf[2][4][4];
        #pragma unroll
        for (int mi = 0; mi < 2; mi++) {
            #pragma unroll
            for (int half = 0; half < 2; half++) {
                const int st = half * 2;
                const int ridx = mi * 2 + half;
                float mx = -1e30f;
                #pragma unroll
                for (int ni = 0; ni < 8; ni++)
                    mx = fmaxf(mx, fmaxf(scf[mi][ni][st], scf[mi][ni][st + 1]));
                mx = fmaxf(mx, __shfl_xor_sync(0xffffffffu, mx, 1));
                mx = fmaxf(mx, __shfl_xor_sync(0xffffffffu, mx, 2));
                float mnew  = fmaxf(mrow[ridx], mx);
                float scale = __expf(mrow[ridx] - mnew);
                mrow[ridx]  = mnew;
                const float cst = -mnew * L2E;
                #pragma unroll
                for (int ni = 0; ni < 8; ni++) {
                    float t0 = fmaf(scf[mi][ni][st],     L2E, cst);
                    float t1 = fmaf(scf[mi][ni][st + 1], L2E, cst);
                    pf[mi][ni >> 1][(ni & 1) * 2 + half] = ex2h2(cvt_f16x2(t0, t1));
                }
                // rescale O and l
                lacc[mi][st]     *= scale;
                lacc[mi][st + 1] *= scale;
                #pragma unroll
                for (int ni = 0; ni < 8; ni++) {
                    o[mi][ni][st]     *= scale;
                    o[mi][ni][st + 1] *= scale;
                }
            }
        }

        // O += P @ V ; l += P @ 1 (ones B fragment). V via ldmatrix.trans.
        #pragma unroll
        for (int kk = 0; kk < 4; kk++) {
            #pragma unroll
            for (int np = 0; np < 4; np++) {
                int row   = kk * 16 + ((lane >> 3) & 1) * 8 + (lane & 7);
                int chunk = np * 2 + (lane >> 4);
                uint32_t bb[4];
                ldsm4t(bb, vab + (uint32_t)(row * AT_S + chunk * 8) * 2);
                mma16(o[0][2*np],   pf[0][kk], bb[0], bb[1]);
                mma16(o[1][2*np],   pf[1][kk], bb[0], bb[1]);
                mma16(o[0][2*np+1], pf[0][kk], bb[2], bb[3]);
                mma16(o[1][2*np+1], pf[1][kk], bb[2], bb[3]);
            }
            mma16(lacc[0], pf[0][kk], ONES_H2, ONES_H2);
            mma16(lacc[1], pf[1][kk], ONES_H2, ONES_H2);
        }
        __syncthreads();
    }

    // Epilogue: normalize, write [B,S,D]. Row sum lives in lacc[mi][half*2].
    const int b_ = bh >> 4;
    const int h  = bh & 15;
    #pragma unroll
    for (int mi = 0; mi < 2; mi++) {
        #pragma unroll
        for (int half = 0; half < 2; half++) {
            const int st = half * 2;
            float inv = 1.0f / lacc[mi][st];
            int s_ = qt * 128 + wid * 32 + mi * 16 + half * 8 + lq;
            float* orow = out + ((size_t)b_ * Sc + s_) * Dc + h * 64;
            #pragma unroll
            for (int ni = 0; ni < 8; ni++) {
                float2 v = { o[mi][ni][st] * inv, o[mi][ni][st + 1] * inv };
                *(float2*)(orow + ni * 8 + lr * 2) = v;
            }
        }
    }
}

// ---------------------------------------------------------------------------
extern "C" void kernel_launch(void* const* d_in, const int* in_sizes, int n_in,
                              void* d_out, int out_size)
{
    const float* x  = (const float*)d_in[0];
    const float* Wq = (const float*)d_in[1];
    const float* bq = (const float*)d_in[2];
    const float* Wk = (const float*)d_in[3];
    const float* bk = (const float*)d_in[4];
    const float* Wv = (const float*)d_in[5];
    const float* bv = (const float*)d_in[6];
    const float* Wg = (const float*)d_in[7];
    const float* bg = (const float*)d_in[8];
    float* out = (float*)d_out;

    cvt_kernel<<<dim3(1024, 5), 256>>>(x, Wq, Wk, Wv, Wg);

    cudaFuncSetAttribute((const void*)proj_kvg,
                         cudaFuncAttributeMaxDynamicSharedMemorySize, PR_SMEM_BYTES);
    cudaFuncSetAttribute((const void*)proj_q,
                         cudaFuncAttributeMaxDynamicSharedMemorySize, PR_SMEM_BYTES);

    dim3 gp3(Dc / 128, (Bc * Sc) / 128, 3);
    proj_kvg<<<gp3, 256, PR_SMEM_BYTES>>>(bk, bv, bg);

    dim3 gpq(Dc / 128, (Bc * Sc) / 128, 1);
    proj_q<<<gpq, 256, PR_SMEM_BYTES>>>(bq);

    cudaFuncSetAttribute((const void*)attn_h,
                         cudaFuncAttributeMaxDynamicSharedMemorySize, AT_SMEM_BYTES);
    attn_h<<<dim3(Sc / 128, Bc * Hc), 128, AT_SMEM_BYTES>>>(out);
}

// round 16
// speedup vs baseline: 1.0649x; 1.0649x over previous
#include <cuda_runtime.h>
#include <cuda_fp16.h>
#include <math.h>
#include <stdint.h>

#define Bc  2
#define Sc  2048
#define Dc  1024
#define Hc  16
#define HDc 64

// Scratch (allocation-free).
__device__ __align__(16) __half g_xh[Bc*Sc*Dc];     // x as fp16 [B*S][D]
__device__ __align__(16) __half g_wh[4*Dc*Dc];      // Wq,Wk,Wv,Wg as fp16 [n][k]
__device__ float               g_qf[Bc*Sc*Dc];      // q proj fp32, head-major
__device__ float               g_gf[Bc*Sc*Dc];      // g proj fp32, head-major
__device__ __align__(16) __half g_kh[Bc*Sc*Dc];     // k fp16, head-major
__device__ __align__(16) __half g_vh[Bc*Sc*Dc];     // v fp16, head-major

// ---------------------------------------------------------------------------
// PTX helpers (all sm_80-era, legal in compute_103 PTX)
// ---------------------------------------------------------------------------
__device__ __forceinline__ uint32_t smem_u32(const void* p) {
    uint32_t a;
    asm("{ .reg .u64 t; cvta.to.shared.u64 t, %1; cvt.u32.u64 %0, t; }"
        : "=r"(a) : "l"(p));
    return a;
}

__device__ __forceinline__ void ldsm4(uint32_t r[4], uint32_t addr) {
    asm volatile("ldmatrix.sync.aligned.m8n8.x4.shared.b16 {%0,%1,%2,%3}, [%4];"
                 : "=r"(r[0]), "=r"(r[1]), "=r"(r[2]), "=r"(r[3]) : "r"(addr));
}

__device__ __forceinline__ void ldsm4t(uint32_t r[4], uint32_t addr) {
    asm volatile("ldmatrix.sync.aligned.m8n8.x4.trans.shared.b16 {%0,%1,%2,%3}, [%4];"
                 : "=r"(r[0]), "=r"(r[1]), "=r"(r[2]), "=r"(r[3]) : "r"(addr));
}

// D += A(16x16) * B(16x8); fp16 inputs, fp32 accumulate.
__device__ __forceinline__ void mma16(float c[4], const uint32_t a[4],
                                      uint32_t b0, uint32_t b1) {
    asm volatile(
        "mma.sync.aligned.m16n8k16.row.col.f32.f16.f16.f32 "
        "{%0,%1,%2,%3}, {%4,%5,%6,%7}, {%8,%9}, {%0,%1,%2,%3};"
        : "+f"(c[0]), "+f"(c[1]), "+f"(c[2]), "+f"(c[3])
        : "r"(a[0]), "r"(a[1]), "r"(a[2]), "r"(a[3]), "r"(b0), "r"(b1));
}

__device__ __forceinline__ void cp16(uint32_t dst, const void* src) {
    asm volatile("cp.async.cg.shared.global [%0], [%1], 16;"
                 :: "r"(dst), "l"(src) : "memory");
}
#define CP_COMMIT() asm volatile("cp.async.commit_group;" ::: "memory")
#define CP_WAIT1()  asm volatile("cp.async.wait_group 1;" ::: "memory")
#define CP_WAIT0()  asm volatile("cp.async.wait_group 0;" ::: "memory")

__device__ __forceinline__ uint32_t packh2(float a, float b) {
    __half2 h = __floats2half2_rn(a, b);
    return *reinterpret_cast<uint32_t*>(&h);
}

// pack (lo,hi) floats -> f16x2, lo in bits[0:15]
__device__ __forceinline__ uint32_t cvt_f16x2(float lo, float hi) {
    uint32_t r;
    asm("cvt.rn.f16x2.f32 %0, %1, %2;" : "=r"(r) : "f"(hi), "f"(lo));
    return r;
}

// elementwise 2^x on f16x2 (MUFU, one op per pair)
__device__ __forceinline__ uint32_t ex2h2(uint32_t t) {
    uint32_t r;
    asm("ex2.approx.f16x2 %0, %1;" : "=r"(r) : "r"(t));
    return r;
}

#define ONES_H2 0x3C003C00u   // half2(1.0, 1.0)
#define L2E     1.4426950408889634f

// ---------------------------------------------------------------------------
// Pre-convert x and W to fp16. grid (1024, 5); each thread reads 2 float4
// and writes ONE 16B uint4 (proven −0.65us vs 4B stores).
// ---------------------------------------------------------------------------
__global__ __launch_bounds__(256)
void cvt_kernel(const float* __restrict__ x,
                const float* __restrict__ Wq, const float* __restrict__ Wk,
                const float* __restrict__ Wv, const float* __restrict__ Wg)
{
    int z = blockIdx.y;
    const float* src; __half* dst; int n8;
    if (z == 0)      { src = x;  dst = g_xh;               n8 = Bc*Sc*Dc/8; }
    else if (z == 1) { src = Wq; dst = g_wh + 0*Dc*Dc;     n8 = Dc*Dc/8; }
    else if (z == 2) { src = Wk; dst = g_wh + 1*Dc*Dc;     n8 = Dc*Dc/8; }
    else if (z == 3) { src = Wv; dst = g_wh + 2*Dc*Dc;     n8 = Dc*Dc/8; }
    else             { src = Wg; dst = g_wh + 3*Dc*Dc;     n8 = Dc*Dc/8; }
    #pragma unroll
    for (int r = 0; r < 2; r++) {
        int i = blockIdx.x * 512 + r * 256 + threadIdx.x;   // 8-elem group idx
        if (i < n8) {
            float4 v0 = ((const float4*)src)[2*i];
            float4 v1 = ((const float4*)src)[2*i + 1];
            uint4 pk;
            pk.x = packh2(v0.x, v0.y);
            pk.y = packh2(v0.z, v0.w);
            pk.z = packh2(v1.x, v1.y);
            pk.w = packh2(v1.z, v1.w);
            ((uint4*)dst)[i] = pk;
        }
    }
}

// ===========================================================================
// Projection GEMM (fp16 mma.sync, 3-STAGE cp.async ring, ONE sync/iter).
// R12 verbatim (proven win). Single launch, all 4 matrices (z = 0..3).
// ===========================================================================
#define PR_STRIDE 40
#define PR_BUF_H  (128 * PR_STRIDE)
#define PR_SMEM_BYTES (6 * PR_BUF_H * 2)     // 61440

__global__ __launch_bounds__(256, 2)
void proj_h(const float* __restrict__ bq, const float* __restrict__ bk,
            const float* __restrict__ bv, const float* __restrict__ bg)
{
    extern __shared__ __half psm[];

    const int z = blockIdx.z;
    const __half* Wg_ = g_wh + (size_t)z * Dc * Dc;
    const float* bias = (z == 0) ? bq : (z == 1) ? bk : (z == 2) ? bv : bg;

    const int tid  = threadIdx.x;
    const int lane = tid & 31;
    const int wid  = tid >> 5;
    const int wm   = wid & 3;
    const int wn   = wid >> 2;
    const int m0   = blockIdx.y * 128;
    const int n0   = blockIdx.x * 128;
    const int lq   = lane >> 2;
    const int lr   = lane & 3;

    const uint32_t xb = smem_u32(psm);
    const uint32_t wb = xb + 3 * PR_BUF_H * 2;

    const int srow = tid >> 2;          // 0..63 base row (2 phases)
    const int sc4  = tid & 3;           // chunk 0..3

    float acc[2][8][4] = {};

    // Prologue: stage tiles 0 and 1 into ring slots 0, 1.
    #pragma unroll
    for (int p = 0; p < 2; p++) {
        const uint32_t boff = (uint32_t)(p * PR_BUF_H) * 2;
        #pragma unroll
        for (int r = 0; r < 2; r++) {
            int row = srow + r * 64;
            uint32_t d = boff + (uint32_t)(row * PR_STRIDE + sc4 * 8) * 2;
            cp16(xb + d, g_xh + (size_t)(m0 + row) * Dc + p * 32 + sc4 * 8);
            cp16(wb + d, Wg_ + (size_t)(n0 + row) * Dc + p * 32 + sc4 * 8);
        }
        CP_COMMIT();
    }

    int bi = 0, si = 2;
    for (int it = 0; it < 32; it++) {
        if (it < 31) { CP_WAIT1(); } else { CP_WAIT0(); }
        __syncthreads();   // data(it) visible AND all reads of slot si finished

        if (it + 2 < 32) {
            const int k0 = (it + 2) * 32;
            const uint32_t xoff = xb + (uint32_t)(si * PR_BUF_H) * 2;
            const uint32_t woff = wb + (uint32_t)(si * PR_BUF_H) * 2;
            #pragma unroll
            for (int r = 0; r < 2; r++) {
                int row = srow + r * 64;
                uint32_t d = (uint32_t)(row * PR_STRIDE + sc4 * 8) * 2;
                cp16(xoff + d, g_xh + (size_t)(m0 + row) * Dc + k0 + sc4 * 8);
                cp16(woff + d, Wg_ + (size_t)(n0 + row) * Dc + k0 + sc4 * 8);
            }
            CP_COMMIT();
        }

        const uint32_t xab = xb + (uint32_t)(bi * PR_BUF_H) * 2;
        const uint32_t wab = wb + (uint32_t)(bi * PR_BUF_H) * 2;
        #pragma unroll
        for (int kk = 0; kk < 2; kk++) {
            uint32_t a[2][4];
            #pragma unroll
            for (int mi = 0; mi < 2; mi++) {
                int row = wm * 32 + mi * 16 + (lane & 15);
                ldsm4(a[mi], xab + (uint32_t)(row * PR_STRIDE + kk * 16 + (lane >> 4) * 8) * 2);
            }
            #pragma unroll
            for (int np = 0; np < 4; np++) {
                int g   = lane >> 3;
                int row = wn * 64 + np * 16 + (g >> 1) * 8 + (lane & 7);
                uint32_t bb[4];
                ldsm4(bb, wab + (uint32_t)(row * PR_STRIDE + kk * 16 + (g & 1) * 8) * 2);
                mma16(acc[0][2*np],   a[0], bb[0], bb[1]);
                mma16(acc[1][2*np],   a[1], bb[0], bb[1]);
                mma16(acc[0][2*np+1], a[0], bb[2], bb[3]);
                mma16(acc[1][2*np+1], a[1], bb[2], bb[3]);
            }
        }
        bi = (bi == 2) ? 0 : bi + 1;
        si = (si == 2) ? 0 : si + 1;
    }

    // Epilogue: bias add + head-major scatter. z 0/3 -> fp32 (q,g); 1/2 -> fp16 (k,v).
    #pragma unroll
    for (int ni = 0; ni < 8; ni++) {
        int col = n0 + wn * 64 + ni * 8 + lr * 2;
        float bx = bias[col], by = bias[col + 1];
        int h  = col >> 6;
        int d0 = col & 63;
        #pragma unroll
        for (int mi = 0; mi < 2; mi++) {
            int mA = m0 + wm * 32 + mi * 16 + lq;
            int mB = mA + 8;
            size_t iA = ((size_t)((mA >> 11) * Hc + h) * Sc + (mA & 2047)) * HDc + d0;
            size_t iB = ((size_t)((mB >> 11) * Hc + h) * Sc + (mB & 2047)) * HDc + d0;
            float a0 = acc[mi][ni][0] + bx, a1 = acc[mi][ni][1] + by;
            float a2 = acc[mi][ni][2] + bx, a3 = acc[mi][ni][3] + by;
            if (z == 1) {
                *(__half2*)(g_kh + iA) = __floats2half2_rn(a0, a1);
                *(__half2*)(g_kh + iB) = __floats2half2_rn(a2, a3);
            } else if (z == 2) {
                *(__half2*)(g_vh + iA) = __floats2half2_rn(a0, a1);
                *(__half2*)(g_vh + iB) = __floats2half2_rn(a2, a3);
            } else {
                float* dst = (z == 0) ? g_qf : g_gf;
                *(float2*)(dst + iA) = make_float2(a0, a1);
                *(float2*)(dst + iB) = make_float2(a2, a3);
            }
        }
    }
}

// ---------------------------------------------------------------------------
__device__ __forceinline__ float gelu_exact(float x) {
    return 0.5f * x * (1.0f + erff(x * 0.7071067811865476f));
}

// ===========================================================================
// Flash attention — R12 verbatim (champion config): fp16 mma with FP32 QK
// accumulate, register P, Q fragments hoisted, gelu-fused Q staging,
// f16x2 exp, tensor-pipe row sums, 2-buffer KV.
// Block: 128 threads / 4 warps, q-tile 128 (warp: 32q x 64t), token-tile 64.
// ===========================================================================
#define AT_S   72
#define QS_H   0
#define KS_H   (128 * AT_S)                 // 9216
#define VS_H   (KS_H + 2 * 64 * AT_S)       // 18432
#define AT_SMEM_BYTES ((VS_H + 2 * 64 * AT_S) * 2)   // 55296

__global__ __launch_bounds__(128, 2)
void attn_h(float* __restrict__ out)
{
    extern __shared__ __half sh[];
    const uint32_t sb = smem_u32(sh);

    const int tid  = threadIdx.x;
    const int lane = tid & 31;
    const int wid  = tid >> 5;
    const int lq   = lane >> 2;
    const int lr   = lane & 3;
    const int qt   = blockIdx.x;      // 0..15
    const int bh   = blockIdx.y;      // 0..31

    const float* Qf = g_qf + ((size_t)bh * Sc + (size_t)qt * 128) * HDc;
    const float* Gf = g_gf + ((size_t)bh * Sc + (size_t)qt * 128) * HDc;
    const __half* Kg = g_kh + (size_t)bh * Sc * HDc;
    const __half* Vg = g_vh + (size_t)bh * Sc * HDc;

    // Stage Q with fused gate: qg = gelu(q*g), fp16 into Qs. One row/thread.
    {
        const float* qrow = Qf + (size_t)tid * HDc;
        const float* grow = Gf + (size_t)tid * HDc;
        #pragma unroll
        for (int c = 0; c < 16; c++) {
            float4 qv = *(const float4*)(qrow + c * 4);
            float4 gv = *(const float4*)(grow + c * 4);
            uint2 pk;
            pk.x = packh2(gelu_exact(qv.x * gv.x), gelu_exact(qv.y * gv.y));
            pk.y = packh2(gelu_exact(qv.z * gv.z), gelu_exact(qv.w * gv.w));
            *(uint2*)(sh + QS_H + tid * AT_S + c * 4) = pk;
        }
    }
    // KV tile 0 via cp.async.
    {
        const int srow = tid >> 3;
        const int sc8  = tid & 7;
        #pragma unroll
        for (int r = 0; r < 4; r++) {
            int row = srow + r * 16;
            uint32_t d = (uint32_t)(row * AT_S + sc8 * 8) * 2;
            cp16(sb + KS_H * 2 + d, Kg + (size_t)row * HDc + sc8 * 8);
            cp16(sb + VS_H * 2 + d, Vg + (size_t)row * HDc + sc8 * 8);
        }
    }
    CP_COMMIT();

    // Q fragments hoisted into registers (loaded ONCE, reused 32 iterations).
    __syncthreads();   // Q stores visible to all lanes before ldsm
    uint32_t qfr[4][2][4];    // [kk][mi][reg]
    #pragma unroll
    for (int kk = 0; kk < 4; kk++) {
        #pragma unroll
        for (int mi = 0; mi < 2; mi++) {
            int row = wid * 32 + mi * 16 + (lane & 15);
            ldsm4(qfr[kk][mi],
                  sb + (uint32_t)(QS_H + row * AT_S + kk * 16 + (lane >> 4) * 8) * 2);
        }
    }

    float o[2][8][4] = {};
    float lacc[2][4] = {};                       // row sums via ones-mma
    float mrow[4] = {-1e30f, -1e30f, -1e30f, -1e30f};

    for (int kt = 0; kt < Sc / 64; kt++) {
        const int buf = kt & 1;
        if (kt + 1 < Sc / 64) {
            const int srow = tid >> 3;
            const int sc8  = tid & 7;
            const uint32_t boff = (uint32_t)((buf ^ 1) * 64 * AT_S) * 2;
            const __half* Kt = Kg + (size_t)(kt + 1) * 64 * HDc;
            const __half* Vt = Vg + (size_t)(kt + 1) * 64 * HDc;
            #pragma unroll
            for (int r = 0; r < 4; r++) {
                int row = srow + r * 16;
                uint32_t d = (uint32_t)(row * AT_S + sc8 * 8) * 2;
                cp16(sb + KS_H * 2 + boff + d, Kt + (size_t)row * HDc + sc8 * 8);
                cp16(sb + VS_H * 2 + boff + d, Vt + (size_t)row * HDc + sc8 * 8);
            }
            CP_COMMIT();
            CP_WAIT1();
        } else {
            CP_WAIT0();
        }
        __syncthreads();

        const uint32_t kab = sb + (uint32_t)(KS_H + buf * 64 * AT_S) * 2;
        const uint32_t vab = sb + (uint32_t)(VS_H + buf * 64 * AT_S) * 2;

        // S = Q @ K^T : 32q x 64t, k = d = 64 (4 k16 steps), Q from registers.
        float scf[2][8][4] = {};
        #pragma unroll
        for (int kk = 0; kk < 4; kk++) {
            #pragma unroll
            for (int np = 0; np < 4; np++) {
                int g   = lane >> 3;
                int row = np * 16 + (g >> 1) * 8 + (lane & 7);
                uint32_t bb[4];
                ldsm4(bb, kab + (uint32_t)(row * AT_S + kk * 16 + (g & 1) * 8) * 2);
                mma16(scf[0][2*np],   qfr[kk][0], bb[0], bb[1]);
                mma16(scf[1][2*np],   qfr[kk][1], bb[0], bb[1]);
                mma16(scf[0][2*np+1], qfr[kk][0], bb[2], bb[3]);
                mma16(scf[1][2*np+1], qfr[kk][1], bb[2], bb[3]);
            }
        }

        // Online softmax: p = exp2((s - m)*log2e) in f16x2 (one MUFU per pair),
        // packed into PV A-fragments. Row sums via ones-mma (below).
        uint32_t pf[2][4][4];
        #pragma unroll
        for (int mi = 0; mi < 2; mi++) {
            #pragma unroll
            for (int half = 0; half < 2; half++) {
                const int st = half * 2;
                const int ridx = mi * 2 + half;
                float mx = -1e30f;
                #pragma unroll
                for (int ni = 0; ni < 8; ni++)
                    mx = fmaxf(mx, fmaxf(scf[mi][ni][st], scf[mi][ni][st + 1]));
                mx = fmaxf(mx, __shfl_xor_sync(0xffffffffu, mx, 1));
                mx = fmaxf(mx, __shfl_xor_sync(0xffffffffu, mx, 2));
                float mnew  = fmaxf(mrow[ridx], mx);
                float scale = __expf(mrow[ridx] - mnew);
                mrow[ridx]  = mnew;
                const float cst = -mnew * L2E;
                #pragma unroll
                for (int ni = 0; ni < 8; ni++) {
                    float t0 = fmaf(scf[mi][ni][st],     L2E, cst);
                    float t1 = fmaf(scf[mi][ni][st + 1], L2E, cst);
                    pf[mi][ni >> 1][(ni & 1) * 2 + half] = ex2h2(cvt_f16x2(t0, t1));
                }
                // rescale O and l
                lacc[mi][st]     *= scale;
                lacc[mi][st + 1] *= scale;
                #pragma unroll
                for (int ni = 0; ni < 8; ni++) {
                    o[mi][ni][st]     *= scale;
                    o[mi][ni][st + 1] *= scale;
                }
            }
        }

        // O += P @ V ; l += P @ 1 (ones B fragment). V via ldmatrix.trans.
        #pragma unroll
        for (int kk = 0; kk < 4; kk++) {
            #pragma unroll
            for (int np = 0; np < 4; np++) {
                int row   = kk * 16 + ((lane >> 3) & 1) * 8 + (lane & 7);
                int chunk = np * 2 + (lane >> 4);
                uint32_t bb[4];
                ldsm4t(bb, vab + (uint32_t)(row * AT_S + chunk * 8) * 2);
                mma16(o[0][2*np],   pf[0][kk], bb[0], bb[1]);
                mma16(o[1][2*np],   pf[1][kk], bb[0], bb[1]);
                mma16(o[0][2*np+1], pf[0][kk], bb[2], bb[3]);
                mma16(o[1][2*np+1], pf[1][kk], bb[2], bb[3]);
            }
            mma16(lacc[0], pf[0][kk], ONES_H2, ONES_H2);
            mma16(lacc[1], pf[1][kk], ONES_H2, ONES_H2);
        }
        __syncthreads();
    }

    // Epilogue: normalize, write [B,S,D]. Row sum lives in lacc[mi][half*2].
    const int b_ = bh >> 4;
    const int h  = bh & 15;
    #pragma unroll
    for (int mi = 0; mi < 2; mi++) {
        #pragma unroll
        for (int half = 0; half < 2; half++) {
            const int st = half * 2;
            float inv = 1.0f / lacc[mi][st];
            int s_ = qt * 128 + wid * 32 + mi * 16 + half * 8 + lq;
            float* orow = out + ((size_t)b_ * Sc + s_) * Dc + h * 64;
            #pragma unroll
            for (int ni = 0; ni < 8; ni++) {
                float2 v = { o[mi][ni][st] * inv, o[mi][ni][st + 1] * inv };
                *(float2*)(orow + ni * 8 + lr * 2) = v;
            }
        }
    }
}

// ---------------------------------------------------------------------------
extern "C" void kernel_launch(void* const* d_in, const int* in_sizes, int n_in,
                              void* d_out, int out_size)
{
    const float* x  = (const float*)d_in[0];
    const float* Wq = (const float*)d_in[1];
    const float* bq = (const float*)d_in[2];
    const float* Wk = (const float*)d_in[3];
    const float* bk = (const float*)d_in[4];
    const float* Wv = (const float*)d_in[5];
    const float* bv = (const float*)d_in[6];
    const float* Wg = (const float*)d_in[7];
    const float* bg = (const float*)d_in[8];
    float* out = (float*)d_out;

    cvt_kernel<<<dim3(1024, 5), 256>>>(x, Wq, Wk, Wv, Wg);

    cudaFuncSetAttribute((const void*)proj_h,
                         cudaFuncAttributeMaxDynamicSharedMemorySize, PR_SMEM_BYTES);
    dim3 gp(Dc / 128, (Bc * Sc) / 128, 4);
    proj_h<<<gp, 256, PR_SMEM_BYTES>>>(bq, bk, bv, bg);

    cudaFuncSetAttribute((const void*)attn_h,
                         cudaFuncAttributeMaxDynamicSharedMemorySize, AT_SMEM_BYTES);
    attn_h<<<dim3(Sc / 128, Bc * Hc), 128, AT_SMEM_BYTES>>>(out);
}